// round 2
// baseline (speedup 1.0000x reference)
#include <cuda_runtime.h>
#include <cstdint>

#define BZ     64
#define NC     2048
#define H      14
#define HW     196
#define NCLS   1000
#define SPLITS 4
#define CPB    512           // channels per block (NC / SPLITS)
#define TILE_C 32
#define NSTAGE 16            // CPB / TILE_C
#define TPB    256
#define PADW   200           // padded channel stride in smem (floats): 16B-aligned, conflict-free
#define NPAIR  105
#define MARGINV 70.0f
#define THRV    125.0f
#define PD_EPS  1e-6f

// scratch (device globals; no allocations allowed)
__device__ float g_G[BZ * SPLITS * NPAIR];
__device__ float g_cam[BZ * SPLITS * 3 * HW];
__device__ float g_rs[BZ * SPLITS * H];
__device__ float g_r[BZ];

// ---------------------------------------------------------------------------
// cp.async prefetch of one 32-channel tile (32 x 196 floats) into padded smem
// ---------------------------------------------------------------------------
__device__ __forceinline__ void prefetch_tile(const float* __restrict__ src_base,
                                              float* dst, int t) {
#pragma unroll
    for (int it = 0; it < 7; it++) {
        int q = t + it * TPB;            // 1568 float4 transfers total (32*49)
        if (q < TILE_C * 49) {
            int cc = q / 49;
            int p4 = q - cc * 49;
            const float* src = src_base + cc * HW + p4 * 4;
            unsigned dsts = (unsigned)__cvta_generic_to_shared(dst + cc * PADW + p4 * 4);
            asm volatile("cp.async.cg.shared.global [%0], [%1], 16;\n"
                         :: "r"(dsts), "l"(src));
        }
    }
}

// ---------------------------------------------------------------------------
// K1: one pass over features -> per-(batch,split): cam0/1/2 (196 each),
//     Gram G (105 upper-tri of sum_c F_c F_c^T), row sums (14)
// ---------------------------------------------------------------------------
__global__ void __launch_bounds__(TPB, 1)
k1_reduce(const float* __restrict__ feat,
          const float* __restrict__ W,
          const int*   __restrict__ idx) {
    extern __shared__ float sh[];
    float* tiles = sh;                               // 3 * TILE_C * PADW floats
    float4* w4  = (float4*)(sh + 3 * TILE_C * PADW); // CPB float4

    const int t   = threadIdx.x;
    const int blk = blockIdx.x;
    const int b   = blk >> 2;
    const int s   = blk & 3;
    const int c0  = s * CPB;

    // gather the 3 weight rows for this block's channel slice, packed float4
    {
        const int i0 = idx[b * 3 + 0];
        const int i1 = idx[b * 3 + 1];
        const int i2 = idx[b * 3 + 2];
        const float* w0 = W + (size_t)i0 * NC;
        const float* w1 = W + (size_t)i1 * NC;
        const float* w2 = W + (size_t)i2 * NC;
        for (int cc = t; cc < CPB; cc += TPB) {
            int c = c0 + cc;
            w4[cc] = make_float4(w0[c], w1[c], w2[c], 0.f);
        }
    }

    const float* fbase = feat + ((size_t)b * NC + c0) * HW;

    // prime 3-deep pipeline
    prefetch_tile(fbase,               tiles,                 t);
    asm volatile("cp.async.commit_group;\n");
    prefetch_tile(fbase + TILE_C * HW, tiles + TILE_C * PADW, t);
    asm volatile("cp.async.commit_group;\n");

    float acc[NPAIR];
#pragma unroll
    for (int i = 0; i < NPAIR; i++) acc[i] = 0.f;
    float cam0 = 0.f, cam1 = 0.f, cam2 = 0.f, rsacc = 0.f;

    const int cl = t >> 3;   // channel within tile (0..31)
    const int j0 = t & 7;    // j-subset start

    for (int st = 0; st < NSTAGE; st++) {
        float* buf = tiles + (st % 3) * TILE_C * PADW;
        if (st + 2 < NSTAGE) {
            prefetch_tile(fbase + (size_t)(st + 2) * TILE_C * HW,
                          tiles + ((st + 2) % 3) * TILE_C * PADW, t);
            asm volatile("cp.async.commit_group;\n");
            asm volatile("cp.async.wait_group 2;\n");
        } else if (st + 1 < NSTAGE) {
            asm volatile("cp.async.wait_group 1;\n");
        } else {
            asm volatile("cp.async.wait_group 0;\n");
        }
        __syncthreads();

        // ---- Gram: each thread owns (channel cl, columns j0, j0+8) ----
        {
            const float* base = buf + cl * PADW;
            for (int jj = j0; jj < H; jj += 8) {
                float col[H];
#pragma unroll
                for (int k = 0; k < H; k++) col[k] = base[k * H + jj];
                int q = 0;
#pragma unroll
                for (int k = 0; k < H; k++) {
#pragma unroll
                    for (int l = k; l < H; l++) {
                        acc[q] = fmaf(col[k], col[l], acc[q]);
                        q++;
                    }
                }
            }
        }

        // ---- CAM + rowsum: pixel-parallel (196 active threads) ----
        if (t < HW) {
            const float4* wrow = w4 + st * TILE_C;
#pragma unroll 4
            for (int cc = 0; cc < TILE_C; cc++) {
                float  f = buf[cc * PADW + t];
                float4 w = wrow[cc];
                cam0 = fmaf(w.x, f, cam0);
                cam1 = fmaf(w.y, f, cam1);
                cam2 = fmaf(w.z, f, cam2);
                rsacc += f;
            }
        }
        __syncthreads();
    }

    // ---- outputs: cam partials + rowsum reduce ----
    if (t < HW) {
        float* co = g_cam + (size_t)blk * 3 * HW;
        co[t]          = cam0;
        co[HW + t]     = cam1;
        co[2 * HW + t] = cam2;
        sh[t] = rsacc;
    }
    __syncthreads();
    if (t < H) {
        float v = 0.f;
#pragma unroll
        for (int j = 0; j < H; j++) v += sh[t * H + j];
        g_rs[blk * H + t] = v;
    }
    __syncthreads();

    // ---- Gram tree reduce 256 -> 32 through shared, then warp shuffle ----
    for (int stride = 128; stride >= 32; stride >>= 1) {
        if (t >= stride && t < 2 * stride) {
            float* d = sh + (t - stride) * NPAIR;
#pragma unroll
            for (int i = 0; i < NPAIR; i++) d[i] = acc[i];
        }
        __syncthreads();
        if (t < stride) {
            const float* srcs = sh + t * NPAIR;
#pragma unroll
            for (int i = 0; i < NPAIR; i++) acc[i] += srcs[i];
        }
        __syncthreads();
    }
    if (t < 32) {
#pragma unroll
        for (int i = 0; i < NPAIR; i++) {
            float v = acc[i];
            v += __shfl_xor_sync(0xffffffffu, v, 16);
            v += __shfl_xor_sync(0xffffffffu, v, 8);
            v += __shfl_xor_sync(0xffffffffu, v, 4);
            v += __shfl_xor_sync(0xffffffffu, v, 2);
            v += __shfl_xor_sync(0xffffffffu, v, 1);
            acc[i] = v;
        }
        for (int i = t; i < NPAIR; i += 32)
            g_G[(size_t)blk * NPAIR + i] = acc[i];
    }
}

// ---------------------------------------------------------------------------
// K2: per-batch finalize -> r[b] = ed1 + clip(70 - d01 - d02) + CE_b
// ---------------------------------------------------------------------------
__global__ void __launch_bounds__(256, 1)
k2_final(const float* __restrict__ pred,
         const int*   __restrict__ cla,
         const float* __restrict__ seg) {
    __shared__ float camr[3][HW];
    __shared__ float D01s[HW];
    __shared__ float D02s[HW];
    __shared__ float dstb[HW];
    __shared__ float Gs[NPAIR];
    __shared__ float rss[H];
    __shared__ float red[256];
    __shared__ float red2[256];
    __shared__ float bc[8];

    const int b = blockIdx.x;
    const int t = threadIdx.x;

    // reduce split partials
    if (t < HW) {
#pragma unroll
        for (int j = 0; j < 3; j++) {
            float v = 0.f;
#pragma unroll
            for (int s = 0; s < SPLITS; s++)
                v += g_cam[((size_t)(b * SPLITS + s) * 3 + j) * HW + t];
            camr[j][t] = v;
        }
    }
    if (t < NPAIR) {
        float v = 0.f;
#pragma unroll
        for (int s = 0; s < SPLITS; s++) v += g_G[(size_t)(b * SPLITS + s) * NPAIR + t];
        Gs[t] = v;
    }
    if (t < H) {
        float v = 0.f;
#pragma unroll
        for (int s = 0; s < SPLITS; s++) v += g_rs[(b * SPLITS + s) * H + t];
        rss[t] = v;
    }
    __syncthreads();

    // per-cam min/max (warp 0)
    if (t < 32) {
        float mn0 = 1e30f, mn1 = 1e30f, mn2 = 1e30f;
        float mx0 = -1e30f, mx1 = -1e30f, mx2 = -1e30f;
        for (int p = t; p < HW; p += 32) {
            float v0 = camr[0][p], v1 = camr[1][p], v2 = camr[2][p];
            mn0 = fminf(mn0, v0); mx0 = fmaxf(mx0, v0);
            mn1 = fminf(mn1, v1); mx1 = fmaxf(mx1, v1);
            mn2 = fminf(mn2, v2); mx2 = fmaxf(mx2, v2);
        }
#pragma unroll
        for (int off = 16; off >= 1; off >>= 1) {
            mn0 = fminf(mn0, __shfl_xor_sync(0xffffffffu, mn0, off));
            mx0 = fmaxf(mx0, __shfl_xor_sync(0xffffffffu, mx0, off));
            mn1 = fminf(mn1, __shfl_xor_sync(0xffffffffu, mn1, off));
            mx1 = fmaxf(mx1, __shfl_xor_sync(0xffffffffu, mx1, off));
            mn2 = fminf(mn2, __shfl_xor_sync(0xffffffffu, mn2, off));
            mx2 = fmaxf(mx2, __shfl_xor_sync(0xffffffffu, mx2, off));
        }
        if (t == 0) {
            bc[0] = mn0; bc[1] = mn1; bc[2] = mn2;
            bc[3] = 255.f / (mx0 - mn0);
            bc[4] = 255.f / (mx1 - mn1);
            bc[5] = 255.f / (mx2 - mn2);
        }
    }
    __syncthreads();

    if (t < HW) {
        float c0 = (camr[0][t] - bc[0]) * bc[3];
        float c1 = (camr[1][t] - bc[1]) * bc[4];
        float c2 = (camr[2][t] - bc[2]) * bc[5];
        D01s[t] = c0 - c1;
        D02s[t] = c0 - c2;
        dstb[t] = (c0 > THRV) ? 1.f : 0.f;
    }
    __syncthreads();

    // <M, G> contraction with symmetry weights (M = D^T D, 105 upper-tri entries)
    float c01 = 0.f, c02 = 0.f;
    if (t < NPAIR) {
        int k = 0, rem = t;
        while (rem >= H - k) { rem -= H - k; k++; }
        int l = k + rem;
        float m01 = 0.f, m02 = 0.f;
#pragma unroll
        for (int i = 0; i < H; i++) {
            m01 = fmaf(D01s[i * H + k], D01s[i * H + l], m01);
            m02 = fmaf(D02s[i * H + k], D02s[i * H + l], m02);
        }
        float wgt = (k == l) ? 1.f : 2.f;
        c01 = wgt * m01 * Gs[t];
        c02 = wgt * m02 * Gs[t];
    }
    red[t]  = c01;
    red2[t] = c02;
    __syncthreads();
    if (t < 32) {
        float s1 = 0.f, s2 = 0.f;
        for (int q = t; q < NPAIR; q += 32) { s1 += red[q]; s2 += red2[q]; }
#pragma unroll
        for (int off = 16; off >= 1; off >>= 1) {
            s1 += __shfl_xor_sync(0xffffffffu, s1, off);
            s2 += __shfl_xor_sync(0xffffffffu, s2, off);
        }
        if (t == 0) { bc[6] = s1; bc[7] = s2; }
    }
    __syncthreads();

    // ed1 rows (pairwise distance of binarized cam0 vs seg truth)
    if (t < H) {
        const float* srow = seg + (size_t)b * HW + t * H;
        float a = 0.f;
#pragma unroll
        for (int w = 0; w < H; w++) {
            float d = dstb[t * H + w] - srow[w] + PD_EPS;
            a = fmaf(d, d, a);
        }
        red[t] = sqrtf(a);
    }
    __syncthreads();

    // cross entropy for this row: logsumexp - pred[truth]
    const float* prow = pred + (size_t)b * NCLS;
    float lm = -1e30f;
    for (int p = t; p < NCLS; p += 256) lm = fmaxf(lm, prow[p]);
    red2[t] = lm;
    __syncthreads();
    for (int stgr = 128; stgr >= 1; stgr >>= 1) {
        if (t < stgr) red2[t] = fmaxf(red2[t], red2[t + stgr]);
        __syncthreads();
    }
    float mx = red2[0];
    __syncthreads();
    float ls = 0.f;
    for (int p = t; p < NCLS; p += 256) ls += expf(prow[p] - mx);
    red2[t] = ls;
    __syncthreads();
    for (int stgr = 128; stgr >= 1; stgr >>= 1) {
        if (t < stgr) red2[t] += red2[t + stgr];
        __syncthreads();
    }

    if (t == 0) {
        float lse = mx + logf(red2[0]);
        float ce  = lse - prow[cla[b]];
        float ed1 = 0.f;
#pragma unroll
        for (int hh = 0; hh < H; hh++) ed1 += red[hh];
        ed1 *= (1.f / H);
        // eps cross terms: 2*eps * (colsum(D) . rowsumF) + eps^2 * HW * NC
        float e01 = 0.f, e02 = 0.f;
#pragma unroll
        for (int k = 0; k < H; k++) {
            float s01 = 0.f, s02 = 0.f;
#pragma unroll
            for (int i = 0; i < H; i++) {
                s01 += D01s[i * H + k];
                s02 += D02s[i * H + k];
            }
            e01 = fmaf(s01, rss[k], e01);
            e02 = fmaf(s02, rss[k], e02);
        }
        const float epsq = PD_EPS * PD_EPS * (float)(HW * NC);
        float d01 = sqrtf(bc[6] + 2.f * PD_EPS * e01 + epsq) * (1.f / NC);
        float d02 = sqrtf(bc[7] + 2.f * PD_EPS * e02 + epsq) * (1.f / NC);
        g_r[b] = red[0] * 0.f + ed1 + fmaxf(MARGINV - d01 - d02, 0.f) + ce;
    }
}

// ---------------------------------------------------------------------------
// K3: mean over batch -> scalar
// ---------------------------------------------------------------------------
__global__ void k3_out(float* __restrict__ out) {
    const int t = threadIdx.x;
    float v = g_r[t];
#pragma unroll
    for (int off = 16; off >= 1; off >>= 1)
        v += __shfl_xor_sync(0xffffffffu, v, off);
    __shared__ float tmp[2];
    if ((t & 31) == 0) tmp[t >> 5] = v;
    __syncthreads();
    if (t == 0) out[0] = (tmp[0] + tmp[1]) * (1.f / BZ);
}

// ---------------------------------------------------------------------------
extern "C" void kernel_launch(void* const* d_in, const int* in_sizes, int n_in,
                              void* d_out, int out_size) {
    const float* pred = (const float*)d_in[0];
    const int*   cla  = (const int*)  d_in[1];
    const float* seg  = (const float*)d_in[2];
    const float* feat = (const float*)d_in[3];
    const float* W    = (const float*)d_in[4];
    const int*   idx  = (const int*)  d_in[5];
    float* out = (float*)d_out;

    const int smem_k1 = (3 * TILE_C * PADW + 4 * CPB) * (int)sizeof(float); // 84992 B
    static bool attr_set = false;
    if (!attr_set) {
        cudaFuncSetAttribute(k1_reduce, cudaFuncAttributeMaxDynamicSharedMemorySize, smem_k1);
        attr_set = true;
    }

    k1_reduce<<<BZ * SPLITS, TPB, smem_k1>>>(feat, W, idx);
    k2_final<<<BZ, 256>>>(pred, cla, seg);
    k3_out<<<1, BZ>>>(out);
}

// round 3
// speedup vs baseline: 2.2667x; 2.2667x over previous
#include <cuda_runtime.h>
#include <cstdint>

#define BZ     64
#define NC     2048
#define H      14
#define HW     196
#define NCLS   1000
#define SPLITS 4
#define CPB    512           // channels per block (NC / SPLITS)
#define TILE_C 16
#define NSTAGE 32            // CPB / TILE_C
#define NBUF   4
#define TPB    256
#define PADW   200           // padded channel stride in smem (floats)
#define NPAIR  105
#define NACC   53            // max pairs per half-group
#define MARGINV 70.0f
#define THRV    125.0f
#define PD_EPS  1e-6f

// scratch (device globals; no allocations allowed)
__device__ float g_G[BZ * SPLITS * NPAIR];
__device__ float g_cam[BZ * SPLITS * 3 * HW];
__device__ float g_rs[BZ * SPLITS * H];
__device__ float g_r[BZ];

// ---------------------------------------------------------------------------
// cp.async prefetch of one 16-channel tile (16 x 196 floats) into padded smem
// ---------------------------------------------------------------------------
__device__ __forceinline__ void prefetch_tile(const float* __restrict__ src_base,
                                              float* dst, int t) {
#pragma unroll
    for (int it = 0; it < 4; it++) {
        int q = t + it * TPB;            // 784 float4 transfers (16*49)
        if (q < TILE_C * 49) {
            int cc = q / 49;
            int p4 = q - cc * 49;
            const float* src = src_base + cc * HW + p4 * 4;
            unsigned dsts = (unsigned)__cvta_generic_to_shared(dst + cc * PADW + p4 * 4);
            asm volatile("cp.async.cg.shared.global [%0], [%1], 16;\n"
                         :: "r"(dsts), "l"(src));
        }
    }
}

// Accumulate this half's share of the 105 upper-tri Gram pairs for column jj.
// After full unroll, q is a literal and the range test folds at compile time.
template<int HALF>
__device__ __forceinline__ void gram_accum(const float* __restrict__ base, int jj,
                                           float* __restrict__ acc) {
    float col[H];
#pragma unroll
    for (int k = 0; k < H; k++) col[k] = base[k * H + jj];
#pragma unroll
    for (int k = 0; k < H; k++) {
#pragma unroll
        for (int l = k; l < H; l++) {
            int q = k * H - (k * (k - 1)) / 2 + (l - k);
            if (HALF == 0) {
                if (q < NACC) acc[q] = fmaf(col[k], col[l], acc[q]);
            } else {
                if (q >= NACC) acc[q - NACC] = fmaf(col[k], col[l], acc[q - NACC]);
            }
        }
    }
}

// ---------------------------------------------------------------------------
// K1: one pass over features -> per-(batch,split): cam0/1/2 (196 each),
//     Gram G (105 upper-tri of sum_c F_c F_c^T), row sums (14)
// ---------------------------------------------------------------------------
__global__ void __launch_bounds__(TPB, 2)
k1_reduce(const float* __restrict__ feat,
          const float* __restrict__ W,
          const int*   __restrict__ idx) {
    extern __shared__ float sh[];
    float* tiles = sh;                                      // NBUF*TILE_C*PADW floats
    float4* w4  = (float4*)(sh + NBUF * TILE_C * PADW);     // CPB float4

    const int t   = threadIdx.x;
    const int blk = blockIdx.x;
    const int b   = blk >> 2;
    const int s   = blk & 3;
    const int c0  = s * CPB;

    const int half = t >> 7;       // warp-uniform pair-half
    const int r    = t & 127;
    const int cl   = r >> 3;       // channel within tile (0..15)
    const int jg   = r & 7;        // column group start

    // gather the 3 weight rows for this block's channel slice, packed float4
    {
        const int i0 = idx[b * 3 + 0];
        const int i1 = idx[b * 3 + 1];
        const int i2 = idx[b * 3 + 2];
        const float* w0 = W + (size_t)i0 * NC;
        const float* w1 = W + (size_t)i1 * NC;
        const float* w2 = W + (size_t)i2 * NC;
        for (int cc = t; cc < CPB; cc += TPB) {
            int c = c0 + cc;
            w4[cc] = make_float4(w0[c], w1[c], w2[c], 0.f);
        }
    }

    const float* fbase = feat + ((size_t)b * NC + c0) * HW;

    // prime 3 stages
    prefetch_tile(fbase,                   tiles,                     t);
    asm volatile("cp.async.commit_group;\n");
    prefetch_tile(fbase +     TILE_C * HW, tiles +     TILE_C * PADW, t);
    asm volatile("cp.async.commit_group;\n");
    prefetch_tile(fbase + 2 * TILE_C * HW, tiles + 2 * TILE_C * PADW, t);
    asm volatile("cp.async.commit_group;\n");

    float acc[NACC];
#pragma unroll
    for (int i = 0; i < NACC; i++) acc[i] = 0.f;
    float cam0 = 0.f, cam1 = 0.f, cam2 = 0.f, rsacc = 0.f;

    for (int st = 0; st < NSTAGE; st++) {
        float* buf = tiles + (st & (NBUF - 1)) * TILE_C * PADW;
        if (st + 3 < NSTAGE) {
            prefetch_tile(fbase + (size_t)(st + 3) * TILE_C * HW,
                          tiles + ((st + 3) & (NBUF - 1)) * TILE_C * PADW, t);
            asm volatile("cp.async.commit_group;\n");
            asm volatile("cp.async.wait_group 3;\n");
        } else if (st + 2 < NSTAGE) {
            asm volatile("cp.async.wait_group 2;\n");
        } else if (st + 1 < NSTAGE) {
            asm volatile("cp.async.wait_group 1;\n");
        } else {
            asm volatile("cp.async.wait_group 0;\n");
        }
        __syncthreads();

        // ---- Gram: thread = (channel cl, columns {jg, jg+8}, pair-half) ----
        {
            const float* base = buf + cl * PADW;
            if (half == 0) {
                gram_accum<0>(base, jg, acc);
                if (jg < 6) gram_accum<0>(base, jg + 8, acc);
            } else {
                gram_accum<1>(base, jg, acc);
                if (jg < 6) gram_accum<1>(base, jg + 8, acc);
            }
        }

        // ---- CAM + rowsum: pixel-parallel (196 active threads) ----
        if (t < HW) {
            const float4* wrow = w4 + st * TILE_C;
#pragma unroll
            for (int cc = 0; cc < TILE_C; cc++) {
                float  f = buf[cc * PADW + t];
                float4 w = wrow[cc];
                cam0 = fmaf(w.x, f, cam0);
                cam1 = fmaf(w.y, f, cam1);
                cam2 = fmaf(w.z, f, cam2);
                rsacc += f;
            }
        }
        __syncthreads();
    }

    // ---- outputs: cam partials + rowsum reduce ----
    if (t < HW) {
        float* co = g_cam + (size_t)blk * 3 * HW;
        co[t]          = cam0;
        co[HW + t]     = cam1;
        co[2 * HW + t] = cam2;
        sh[t] = rsacc;
    }
    __syncthreads();
    if (t < H) {
        float v = 0.f;
#pragma unroll
        for (int j = 0; j < H; j++) v += sh[t * H + j];
        g_rs[blk * H + t] = v;
    }
    __syncthreads();

    // ---- Gram reduce: dump all accs, 105 threads sum 128 partials each ----
    {
        float* d = sh + (size_t)(half * 128 + r) * NACC;
#pragma unroll
        for (int i = 0; i < NACC; i++) d[i] = acc[i];
    }
    __syncthreads();
    if (t < NPAIR) {
        const int hh    = (t < NACC) ? 0 : 1;
        const int local = (hh == 0) ? t : t - NACC;
        const float* sp = sh + (size_t)hh * 128 * NACC + local;
        float v = 0.f;
#pragma unroll 8
        for (int rr = 0; rr < 128; rr++) v += sp[rr * NACC];
        g_G[(size_t)blk * NPAIR + t] = v;
    }
}

// ---------------------------------------------------------------------------
// K2: per-batch finalize -> r[b] = ed1 + clip(70 - d01 - d02) + CE_b
// ---------------------------------------------------------------------------
__global__ void __launch_bounds__(256, 1)
k2_final(const float* __restrict__ pred,
         const int*   __restrict__ cla,
         const float* __restrict__ seg) {
    __shared__ float camr[3][HW];
    __shared__ float D01s[HW];
    __shared__ float D02s[HW];
    __shared__ float dstb[HW];
    __shared__ float Gs[NPAIR];
    __shared__ float rss[H];
    __shared__ float red[256];
    __shared__ float red2[256];
    __shared__ float bc[8];

    const int b = blockIdx.x;
    const int t = threadIdx.x;

    // reduce split partials
    if (t < HW) {
#pragma unroll
        for (int j = 0; j < 3; j++) {
            float v = 0.f;
#pragma unroll
            for (int s = 0; s < SPLITS; s++)
                v += g_cam[((size_t)(b * SPLITS + s) * 3 + j) * HW + t];
            camr[j][t] = v;
        }
    }
    if (t < NPAIR) {
        float v = 0.f;
#pragma unroll
        for (int s = 0; s < SPLITS; s++) v += g_G[(size_t)(b * SPLITS + s) * NPAIR + t];
        Gs[t] = v;
    }
    if (t < H) {
        float v = 0.f;
#pragma unroll
        for (int s = 0; s < SPLITS; s++) v += g_rs[(b * SPLITS + s) * H + t];
        rss[t] = v;
    }
    __syncthreads();

    // per-cam min/max (warp 0)
    if (t < 32) {
        float mn0 = 1e30f, mn1 = 1e30f, mn2 = 1e30f;
        float mx0 = -1e30f, mx1 = -1e30f, mx2 = -1e30f;
        for (int p = t; p < HW; p += 32) {
            float v0 = camr[0][p], v1 = camr[1][p], v2 = camr[2][p];
            mn0 = fminf(mn0, v0); mx0 = fmaxf(mx0, v0);
            mn1 = fminf(mn1, v1); mx1 = fmaxf(mx1, v1);
            mn2 = fminf(mn2, v2); mx2 = fmaxf(mx2, v2);
        }
#pragma unroll
        for (int off = 16; off >= 1; off >>= 1) {
            mn0 = fminf(mn0, __shfl_xor_sync(0xffffffffu, mn0, off));
            mx0 = fmaxf(mx0, __shfl_xor_sync(0xffffffffu, mx0, off));
            mn1 = fminf(mn1, __shfl_xor_sync(0xffffffffu, mn1, off));
            mx1 = fmaxf(mx1, __shfl_xor_sync(0xffffffffu, mx1, off));
            mn2 = fminf(mn2, __shfl_xor_sync(0xffffffffu, mn2, off));
            mx2 = fmaxf(mx2, __shfl_xor_sync(0xffffffffu, mx2, off));
        }
        if (t == 0) {
            bc[0] = mn0; bc[1] = mn1; bc[2] = mn2;
            bc[3] = 255.f / (mx0 - mn0);
            bc[4] = 255.f / (mx1 - mn1);
            bc[5] = 255.f / (mx2 - mn2);
        }
    }
    __syncthreads();

    if (t < HW) {
        float c0 = (camr[0][t] - bc[0]) * bc[3];
        float c1 = (camr[1][t] - bc[1]) * bc[4];
        float c2 = (camr[2][t] - bc[2]) * bc[5];
        D01s[t] = c0 - c1;
        D02s[t] = c0 - c2;
        dstb[t] = (c0 > THRV) ? 1.f : 0.f;
    }
    __syncthreads();

    // <M, G> contraction with symmetry weights (M = D^T D, 105 upper-tri)
    float c01 = 0.f, c02 = 0.f;
    if (t < NPAIR) {
        int k = 0, rem = t;
        while (rem >= H - k) { rem -= H - k; k++; }
        int l = k + rem;
        float m01 = 0.f, m02 = 0.f;
#pragma unroll
        for (int i = 0; i < H; i++) {
            m01 = fmaf(D01s[i * H + k], D01s[i * H + l], m01);
            m02 = fmaf(D02s[i * H + k], D02s[i * H + l], m02);
        }
        float wgt = (k == l) ? 1.f : 2.f;
        c01 = wgt * m01 * Gs[t];
        c02 = wgt * m02 * Gs[t];
    }
    red[t]  = c01;
    red2[t] = c02;
    __syncthreads();
    if (t < 32) {
        float s1 = 0.f, s2 = 0.f;
        for (int q = t; q < NPAIR; q += 32) { s1 += red[q]; s2 += red2[q]; }
#pragma unroll
        for (int off = 16; off >= 1; off >>= 1) {
            s1 += __shfl_xor_sync(0xffffffffu, s1, off);
            s2 += __shfl_xor_sync(0xffffffffu, s2, off);
        }
        if (t == 0) { bc[6] = s1; bc[7] = s2; }
    }
    __syncthreads();

    // ed1 rows (pairwise distance of binarized cam0 vs seg truth)
    if (t < H) {
        const float* srow = seg + (size_t)b * HW + t * H;
        float a = 0.f;
#pragma unroll
        for (int w = 0; w < H; w++) {
            float d = dstb[t * H + w] - srow[w] + PD_EPS;
            a = fmaf(d, d, a);
        }
        red[t] = sqrtf(a);
    }
    __syncthreads();

    // cross entropy for this row: logsumexp - pred[truth]
    const float* prow = pred + (size_t)b * NCLS;
    float lm = -1e30f;
    for (int p = t; p < NCLS; p += 256) lm = fmaxf(lm, prow[p]);
    red2[t] = lm;
    __syncthreads();
    for (int stgr = 128; stgr >= 1; stgr >>= 1) {
        if (t < stgr) red2[t] = fmaxf(red2[t], red2[t + stgr]);
        __syncthreads();
    }
    float mx = red2[0];
    __syncthreads();
    float ls = 0.f;
    for (int p = t; p < NCLS; p += 256) ls += expf(prow[p] - mx);
    red2[t] = ls;
    __syncthreads();
    for (int stgr = 128; stgr >= 1; stgr >>= 1) {
        if (t < stgr) red2[t] += red2[t + stgr];
        __syncthreads();
    }

    if (t == 0) {
        float lse = mx + logf(red2[0]);
        float ce  = lse - prow[cla[b]];
        float ed1 = 0.f;
#pragma unroll
        for (int hh = 0; hh < H; hh++) ed1 += red[hh];
        ed1 *= (1.f / H);
        // eps cross terms: 2*eps * (colsum(D) . rowsumF) + eps^2 * HW * NC
        float e01 = 0.f, e02 = 0.f;
#pragma unroll
        for (int k = 0; k < H; k++) {
            float s01 = 0.f, s02 = 0.f;
#pragma unroll
            for (int i = 0; i < H; i++) {
                s01 += D01s[i * H + k];
                s02 += D02s[i * H + k];
            }
            e01 = fmaf(s01, rss[k], e01);
            e02 = fmaf(s02, rss[k], e02);
        }
        const float epsq = PD_EPS * PD_EPS * (float)(HW * NC);
        float d01 = sqrtf(bc[6] + 2.f * PD_EPS * e01 + epsq) * (1.f / NC);
        float d02 = sqrtf(bc[7] + 2.f * PD_EPS * e02 + epsq) * (1.f / NC);
        g_r[b] = ed1 + fmaxf(MARGINV - d01 - d02, 0.f) + ce;
    }
}

// ---------------------------------------------------------------------------
// K3: mean over batch -> scalar
// ---------------------------------------------------------------------------
__global__ void k3_out(float* __restrict__ out) {
    const int t = threadIdx.x;
    float v = g_r[t];
#pragma unroll
    for (int off = 16; off >= 1; off >>= 1)
        v += __shfl_xor_sync(0xffffffffu, v, off);
    __shared__ float tmp[2];
    if ((t & 31) == 0) tmp[t >> 5] = v;
    __syncthreads();
    if (t == 0) out[0] = (tmp[0] + tmp[1]) * (1.f / BZ);
}

// ---------------------------------------------------------------------------
extern "C" void kernel_launch(void* const* d_in, const int* in_sizes, int n_in,
                              void* d_out, int out_size) {
    const float* pred = (const float*)d_in[0];
    const int*   cla  = (const int*)  d_in[1];
    const float* seg  = (const float*)d_in[2];
    const float* feat = (const float*)d_in[3];
    const float* W    = (const float*)d_in[4];
    const int*   idx  = (const int*)  d_in[5];
    float* out = (float*)d_out;

    // tiles (4*16*200) + w4 (512 float4) = 12800 + 2048 floats = 59392 B
    const int smem_k1 = (NBUF * TILE_C * PADW + 4 * CPB) * (int)sizeof(float);
    cudaFuncSetAttribute(k1_reduce, cudaFuncAttributeMaxDynamicSharedMemorySize, smem_k1);

    k1_reduce<<<BZ * SPLITS, TPB, smem_k1>>>(feat, W, idx);
    k2_final<<<BZ, 256>>>(pred, cla, seg);
    k3_out<<<1, BZ>>>(out);
}

// round 4
// speedup vs baseline: 2.4831x; 1.0955x over previous
#include <cuda_runtime.h>
#include <cstdint>

#define BZ     64
#define NC     2048
#define H      14
#define HW     196
#define NCLS   1000
#define SPLITS 4
#define CPB    512
#define TILE_C 16
#define NSTAGE 32            // CPB / TILE_C
#define NBUF   5
#define TPB    256
#define PADW   200
#define NPAIR  105
#define MARGINV 70.0f
#define THRV    125.0f
#define PD_EPS  1e-6f

typedef unsigned long long ull;

// scratch (device globals; no allocations allowed)
__device__ float g_G[BZ * SPLITS * NPAIR];
__device__ float g_cam[BZ * SPLITS * 3 * HW];
__device__ float g_rs[BZ * SPLITS * H];
__device__ float g_cem[BZ * SPLITS];
__device__ float g_ces[BZ * SPLITS];
__device__ float g_r[BZ];

// ---------------- f32x2 helpers ----------------
__device__ __forceinline__ ull pk2(float lo, float hi) {
    ull r; asm("mov.b64 %0,{%1,%2};" : "=l"(r) : "f"(lo), "f"(hi)); return r;
}
__device__ __forceinline__ void upk2(float& lo, float& hi, ull v) {
    asm("mov.b64 {%0,%1},%2;" : "=f"(lo), "=f"(hi) : "l"(v));
}
__device__ __forceinline__ ull fma2(ull a, ull b, ull c) {
    ull d; asm("fma.rn.f32x2 %0,%1,%2,%3;" : "=l"(d) : "l"(a), "l"(b), "l"(c)); return d;
}
__device__ __forceinline__ ull add2(ull a, ull b) {
    ull d; asm("add.rn.f32x2 %0,%1,%2;" : "=l"(d) : "l"(a), "l"(b)); return d;
}

// packed-acc offsets: half0 (k even): O0(kk)=7kk-kk(kk-1)/2 ; half1: O1(kk)=6kk-kk(kk-1)/2
__device__ __forceinline__ int O0f(int kk) { return 7 * kk - (kk * (kk - 1)) / 2; }
__device__ __forceinline__ int O1f(int kk) { return 6 * kk - (kk * (kk - 1)) / 2; }

// ---------------------------------------------------------------------------
// cp.async prefetch of one 16-channel tile (16 x 196 floats) into padded smem
// ---------------------------------------------------------------------------
__device__ __forceinline__ void prefetch_tile(const float* __restrict__ src_base,
                                              float* dst, int t) {
#pragma unroll
    for (int it = 0; it < 4; it++) {
        int q = t + it * TPB;            // 784 float4 transfers (16*49)
        if (q < TILE_C * 49) {
            int cc = q / 49;
            int p4 = q - cc * 49;
            const float* src = src_base + cc * HW + p4 * 4;
            unsigned dsts = (unsigned)__cvta_generic_to_shared(dst + cc * PADW + p4 * 4);
            asm volatile("cp.async.cg.shared.global [%0], [%1], 16;\n"
                         :: "r"(dsts), "l"(src));
        }
    }
}

// one column jj of one channel: load 14 strided floats packed, accumulate pairs
template<int HALF>
__device__ __forceinline__ void gram_col(const float* __restrict__ base, int jj,
                                         ull* __restrict__ ap, float* __restrict__ ad) {
    ull c2[7];
#pragma unroll
    for (int m = 0; m < 7; m++) {
        float a = base[(2 * m) * H + jj];
        float b = base[(2 * m + 1) * H + jj];
        c2[m] = pk2(a, b);
    }
    if (HALF == 0) {
#pragma unroll
        for (int kk = 0; kk < 7; kk++) {     // k = 2kk
            float lo, hi; upk2(lo, hi, c2[kk]);
            ull sp = pk2(lo, lo);
#pragma unroll
            for (int m = kk; m < 7; m++)
                ap[O0f(kk) + m - kk] = fma2(sp, c2[m], ap[O0f(kk) + m - kk]);
        }
    } else {
#pragma unroll
        for (int kk = 0; kk < 7; kk++) {     // k = 2kk+1
            float lo, hi; upk2(lo, hi, c2[kk]);
            ad[kk] = fmaf(hi, hi, ad[kk]);   // diagonal (k,k)
            ull sp = pk2(hi, hi);
#pragma unroll
            for (int m = kk + 1; m < 7; m++)
                ap[O1f(kk) + m - kk - 1] = fma2(sp, c2[m], ap[O1f(kk) + m - kk - 1]);
        }
    }
}

// ---------------------------------------------------------------------------
// K1: streams features once; emits per-(batch,split) cams, Gram, rowsums + CE partial
// smem main layout (floats): tiles[0,16000) wpk[16000,17024) wqk[17024,18048) ce[18048,18304)
// smem reduce layout: slab0 128x29 ull, slab1 128x22 ull, slabd 128x8 f
// ---------------------------------------------------------------------------
__global__ void __launch_bounds__(TPB, 2)
k1_reduce(const float* __restrict__ feat,
          const float* __restrict__ W,
          const int*   __restrict__ idx,
          const float* __restrict__ pred) {
    extern __shared__ float sh[];
    float* tiles = sh;
    ull*   wpk   = (ull*)(sh + NBUF * TILE_C * PADW);          // {w0,w1}
    ull*   wqk   = wpk + CPB;                                  // {w2,1.0}
    float* cesh  = sh + NBUF * TILE_C * PADW + 4 * CPB;        // 256 floats

    const int t   = threadIdx.x;
    const int blk = blockIdx.x;
    const int b   = blk >> 2;
    const int s   = blk & 3;
    const int c0  = s * CPB;

    const int half = t >> 7;
    const int r    = t & 127;
    const int cl   = r >> 3;       // channel in tile (0..15)
    const int jg   = r & 7;        // column group

    // weight gather (packed)
    {
        const int i0 = idx[b * 3 + 0];
        const int i1 = idx[b * 3 + 1];
        const int i2 = idx[b * 3 + 2];
        const float* w0 = W + (size_t)i0 * NC;
        const float* w1 = W + (size_t)i1 * NC;
        const float* w2 = W + (size_t)i2 * NC;
        for (int cc = t; cc < CPB; cc += TPB) {
            int c = c0 + cc;
            wpk[cc] = pk2(w0[c], w1[c]);
            wqk[cc] = pk2(w2[c], 1.0f);
        }
    }

    const float* fbase = feat + ((size_t)b * NC + c0) * HW;

    // prime pipeline (prefetch distance 3, 5 buffers)
    prefetch_tile(fbase,                   tiles,                 t);
    asm volatile("cp.async.commit_group;\n");
    prefetch_tile(fbase +     TILE_C * HW, tiles +     TILE_C * PADW, t);
    asm volatile("cp.async.commit_group;\n");
    prefetch_tile(fbase + 2 * TILE_C * HW, tiles + 2 * TILE_C * PADW, t);
    asm volatile("cp.async.commit_group;\n");

    // ---- CE partial over classes [s*250, s*250+250) (overlaps prefetch) ----
    {
        const float* prow = pred + (size_t)b * NCLS + s * 250;
        float x = (t < 250) ? prow[t] : -1e30f;
        float m = x;
#pragma unroll
        for (int off = 16; off >= 1; off >>= 1)
            m = fmaxf(m, __shfl_xor_sync(0xffffffffu, m, off));
        if ((t & 31) == 0) cesh[t >> 5] = m;
        __syncthreads();
        float mx = cesh[0];
#pragma unroll
        for (int w = 1; w < 8; w++) mx = fmaxf(mx, cesh[w]);
        float e = (t < 250) ? __expf(x - mx) * 0.0f + expf(x - mx) : 0.0f;
#pragma unroll
        for (int off = 16; off >= 1; off >>= 1)
            e += __shfl_xor_sync(0xffffffffu, e, off);
        __syncthreads();
        if ((t & 31) == 0) cesh[8 + (t >> 5)] = e;
        __syncthreads();
        if (t == 0) {
            float sum = 0.f;
#pragma unroll
            for (int w = 0; w < 8; w++) sum += cesh[8 + w];
            g_cem[blk] = mx;
            g_ces[blk] = sum;
        }
    }

    ull  ap[28];
    float ad[7];
#pragma unroll
    for (int i = 0; i < 28; i++) ap[i] = 0ull;
#pragma unroll
    for (int i = 0; i < 7; i++) ad[i] = 0.f;
    ull cam01 = 0ull, cam2r = 0ull;

    int rdbuf = 0;
    for (int st = 0; st < NSTAGE; st++) {
        if (st + 3 < NSTAGE) {
            int wb = st + 3;
            int wbuf = wb - (wb / NBUF) * NBUF;
            prefetch_tile(fbase + (size_t)wb * TILE_C * HW,
                          tiles + wbuf * TILE_C * PADW, t);
            asm volatile("cp.async.commit_group;\n");
            asm volatile("cp.async.wait_group 3;\n");
        } else if (st + 2 < NSTAGE) {
            asm volatile("cp.async.wait_group 2;\n");
        } else if (st + 1 < NSTAGE) {
            asm volatile("cp.async.wait_group 1;\n");
        } else {
            asm volatile("cp.async.wait_group 0;\n");
        }
        __syncthreads();

        const float* buf = tiles + rdbuf * TILE_C * PADW;
        rdbuf = (rdbuf + 1 == NBUF) ? 0 : rdbuf + 1;

        // ---- Gram (packed f32x2) ----
        {
            const float* base = buf + cl * PADW;
            if (half == 0) {
                gram_col<0>(base, jg, ap, ad);
                if (jg < 6) gram_col<0>(base, jg + 8, ap, ad);
            } else {
                gram_col<1>(base, jg, ap, ad);
                if (jg < 6) gram_col<1>(base, jg + 8, ap, ad);
            }
        }

        // ---- CAM + rowsum (packed): cam01={cam0,cam1}, cam2r={cam2,rowsum} ----
        if (t < HW) {
            const ull* wp = wpk + st * TILE_C;
            const ull* wq = wqk + st * TILE_C;
#pragma unroll
            for (int cc = 0; cc < TILE_C; cc++) {
                float f = buf[cc * PADW + t];
                ull fs = pk2(f, f);
                cam01 = fma2(fs, wp[cc], cam01);
                cam2r = fma2(fs, wq[cc], cam2r);
            }
        }
    }
    __syncthreads();   // all reads of last tile done before smem repurpose

    // ---- cam + rowsum outputs ----
    if (t < HW) {
        float a, bb, c, rs;
        upk2(a, bb, cam01);
        upk2(c, rs, cam2r);
        float* co = g_cam + (size_t)blk * 3 * HW;
        co[t]          = a;
        co[HW + t]     = bb;
        co[2 * HW + t] = c;
        sh[t] = rs;
    }
    __syncthreads();
    if (t < H) {
        float v = 0.f;
#pragma unroll
        for (int j = 0; j < H; j++) v += sh[t * H + j];
        g_rs[blk * H + t] = v;
    }
    __syncthreads();

    // ---- Gram dump (packed) ----
    ull*   slab0 = (ull*)sh;                 // 128 x 29
    ull*   slab1 = slab0 + 128 * 29;         // 128 x 22
    float* slabd = (float*)(slab1 + 128 * 22); // 128 x 8
    if (half == 0) {
        ull* d = slab0 + (size_t)r * 29;
#pragma unroll
        for (int i = 0; i < 28; i++) d[i] = ap[i];
    } else {
        ull* d = slab1 + (size_t)r * 22;
#pragma unroll
        for (int i = 0; i < 21; i++) d[i] = ap[i];
        float* dd = slabd + (size_t)r * 8;
#pragma unroll
        for (int i = 0; i < 7; i++) dd[i] = ad[i];
    }
    __syncthreads();

    float* gg = g_G + (size_t)blk * NPAIR;
    if (t < 28) {
        int tau = t;
        int kk = 0;
        while (kk < 6 && O0f(kk + 1) <= tau) kk++;
        int m = kk + (tau - O0f(kk));
        int k = 2 * kk, l0 = 2 * m;
        ull S = 0ull;
#pragma unroll 8
        for (int rr = 0; rr < 128; rr++) S = add2(S, slab0[(size_t)rr * 29 + tau]);
        float a, bb; upk2(a, bb, S);
        int q = k * 14 - (k * (k - 1)) / 2 + (l0 - k);
        gg[q] = a; gg[q + 1] = bb;
    } else if (t >= 32 && t < 53) {
        int tau = t - 32;
        int kk = 0;
        while (kk < 6 && O1f(kk + 1) <= tau) kk++;
        int m = kk + 1 + (tau - O1f(kk));
        int k = 2 * kk + 1, l0 = 2 * m;
        ull S = 0ull;
#pragma unroll 8
        for (int rr = 0; rr < 128; rr++) S = add2(S, slab1[(size_t)rr * 22 + tau]);
        float a, bb; upk2(a, bb, S);
        int q = k * 14 - (k * (k - 1)) / 2 + (l0 - k);
        gg[q] = a; gg[q + 1] = bb;
    } else if (t >= 64 && t < 71) {
        int kk = t - 64;
        int k = 2 * kk + 1;
        float v = 0.f;
#pragma unroll 8
        for (int rr = 0; rr < 128; rr++) v += slabd[(size_t)rr * 8 + kk];
        int q = k * 14 - (k * (k - 1)) / 2;
        gg[q] = v;
    }
}

// ---------------------------------------------------------------------------
// K2: per-batch finalize -> r[b] = ed1 + clip(70 - d01 - d02) + CE_b
// ---------------------------------------------------------------------------
__global__ void __launch_bounds__(256, 1)
k2_final(const float* __restrict__ pred,
         const int*   __restrict__ cla,
         const float* __restrict__ seg) {
    __shared__ float camr[3][HW];
    __shared__ float D01s[HW];
    __shared__ float D02s[HW];
    __shared__ float dstb[HW];
    __shared__ float Gs[NPAIR];
    __shared__ float rss[H];
    __shared__ float red[256];
    __shared__ float red2[256];
    __shared__ float bc[8];

    const int b = blockIdx.x;
    const int t = threadIdx.x;

    if (t < HW) {
#pragma unroll
        for (int j = 0; j < 3; j++) {
            float v = 0.f;
#pragma unroll
            for (int s = 0; s < SPLITS; s++)
                v += g_cam[((size_t)(b * SPLITS + s) * 3 + j) * HW + t];
            camr[j][t] = v;
        }
    }
    if (t < NPAIR) {
        float v = 0.f;
#pragma unroll
        for (int s = 0; s < SPLITS; s++) v += g_G[(size_t)(b * SPLITS + s) * NPAIR + t];
        Gs[t] = v;
    }
    if (t < H) {
        float v = 0.f;
#pragma unroll
        for (int s = 0; s < SPLITS; s++) v += g_rs[(b * SPLITS + s) * H + t];
        rss[t] = v;
    }
    __syncthreads();

    if (t < 32) {
        float mn0 = 1e30f, mn1 = 1e30f, mn2 = 1e30f;
        float mx0 = -1e30f, mx1 = -1e30f, mx2 = -1e30f;
        for (int p = t; p < HW; p += 32) {
            float v0 = camr[0][p], v1 = camr[1][p], v2 = camr[2][p];
            mn0 = fminf(mn0, v0); mx0 = fmaxf(mx0, v0);
            mn1 = fminf(mn1, v1); mx1 = fmaxf(mx1, v1);
            mn2 = fminf(mn2, v2); mx2 = fmaxf(mx2, v2);
        }
#pragma unroll
        for (int off = 16; off >= 1; off >>= 1) {
            mn0 = fminf(mn0, __shfl_xor_sync(0xffffffffu, mn0, off));
            mx0 = fmaxf(mx0, __shfl_xor_sync(0xffffffffu, mx0, off));
            mn1 = fminf(mn1, __shfl_xor_sync(0xffffffffu, mn1, off));
            mx1 = fmaxf(mx1, __shfl_xor_sync(0xffffffffu, mx1, off));
            mn2 = fminf(mn2, __shfl_xor_sync(0xffffffffu, mn2, off));
            mx2 = fmaxf(mx2, __shfl_xor_sync(0xffffffffu, mx2, off));
        }
        if (t == 0) {
            bc[0] = mn0; bc[1] = mn1; bc[2] = mn2;
            bc[3] = 255.f / (mx0 - mn0);
            bc[4] = 255.f / (mx1 - mn1);
            bc[5] = 255.f / (mx2 - mn2);
        }
    }
    __syncthreads();

    if (t < HW) {
        float c0 = (camr[0][t] - bc[0]) * bc[3];
        float c1 = (camr[1][t] - bc[1]) * bc[4];
        float c2 = (camr[2][t] - bc[2]) * bc[5];
        D01s[t] = c0 - c1;
        D02s[t] = c0 - c2;
        dstb[t] = (c0 > THRV) ? 1.f : 0.f;
    }
    __syncthreads();

    float c01 = 0.f, c02 = 0.f;
    if (t < NPAIR) {
        int k = 0, rem = t;
        while (rem >= H - k) { rem -= H - k; k++; }
        int l = k + rem;
        float m01 = 0.f, m02 = 0.f;
#pragma unroll
        for (int i = 0; i < H; i++) {
            m01 = fmaf(D01s[i * H + k], D01s[i * H + l], m01);
            m02 = fmaf(D02s[i * H + k], D02s[i * H + l], m02);
        }
        float wgt = (k == l) ? 1.f : 2.f;
        c01 = wgt * m01 * Gs[t];
        c02 = wgt * m02 * Gs[t];
    }
    red[t]  = c01;
    red2[t] = c02;
    __syncthreads();
    if (t < 32) {
        float s1 = 0.f, s2 = 0.f;
        for (int q = t; q < NPAIR; q += 32) { s1 += red[q]; s2 += red2[q]; }
#pragma unroll
        for (int off = 16; off >= 1; off >>= 1) {
            s1 += __shfl_xor_sync(0xffffffffu, s1, off);
            s2 += __shfl_xor_sync(0xffffffffu, s2, off);
        }
        if (t == 0) { bc[6] = s1; bc[7] = s2; }
    }
    __syncthreads();

    if (t < H) {
        const float* srow = seg + (size_t)b * HW + t * H;
        float a = 0.f;
#pragma unroll
        for (int w = 0; w < H; w++) {
            float d = dstb[t * H + w] - srow[w] + PD_EPS;
            a = fmaf(d, d, a);
        }
        red[t] = sqrtf(a);
    }
    __syncthreads();

    if (t == 0) {
        // CE merge from partials
        float m0 = g_cem[b * 4 + 0], m1 = g_cem[b * 4 + 1];
        float m2 = g_cem[b * 4 + 2], m3 = g_cem[b * 4 + 3];
        float M = fmaxf(fmaxf(m0, m1), fmaxf(m2, m3));
        float S = g_ces[b * 4 + 0] * expf(m0 - M) + g_ces[b * 4 + 1] * expf(m1 - M)
                + g_ces[b * 4 + 2] * expf(m2 - M) + g_ces[b * 4 + 3] * expf(m3 - M);
        float lse = M + logf(S);
        float ce  = lse - pred[(size_t)b * NCLS + cla[b]];

        float ed1 = 0.f;
#pragma unroll
        for (int hh = 0; hh < H; hh++) ed1 += red[hh];
        ed1 *= (1.f / H);

        float e01 = 0.f, e02 = 0.f;
#pragma unroll
        for (int k = 0; k < H; k++) {
            float s01 = 0.f, s02 = 0.f;
#pragma unroll
            for (int i = 0; i < H; i++) {
                s01 += D01s[i * H + k];
                s02 += D02s[i * H + k];
            }
            e01 = fmaf(s01, rss[k], e01);
            e02 = fmaf(s02, rss[k], e02);
        }
        const float epsq = PD_EPS * PD_EPS * (float)(HW * NC);
        float d01 = sqrtf(bc[6] + 2.f * PD_EPS * e01 + epsq) * (1.f / NC);
        float d02 = sqrtf(bc[7] + 2.f * PD_EPS * e02 + epsq) * (1.f / NC);
        g_r[b] = ed1 + fmaxf(MARGINV - d01 - d02, 0.f) + ce;
    }
}

// ---------------------------------------------------------------------------
__global__ void k3_out(float* __restrict__ out) {
    const int t = threadIdx.x;
    float v = g_r[t];
#pragma unroll
    for (int off = 16; off >= 1; off >>= 1)
        v += __shfl_xor_sync(0xffffffffu, v, off);
    __shared__ float tmp[2];
    if ((t & 31) == 0) tmp[t >> 5] = v;
    __syncthreads();
    if (t == 0) out[0] = (tmp[0] + tmp[1]) * (1.f / BZ);
}

// ---------------------------------------------------------------------------
extern "C" void kernel_launch(void* const* d_in, const int* in_sizes, int n_in,
                              void* d_out, int out_size) {
    const float* pred = (const float*)d_in[0];
    const int*   cla  = (const int*)  d_in[1];
    const float* seg  = (const float*)d_in[2];
    const float* feat = (const float*)d_in[3];
    const float* W    = (const float*)d_in[4];
    const int*   idx  = (const int*)  d_in[5];
    float* out = (float*)d_out;

    // tiles 5*16*200 + w 2*512*2 + ce 256 = 18304 floats = 73216 B
    const int smem_k1 = (NBUF * TILE_C * PADW + 4 * CPB + 256) * (int)sizeof(float);
    cudaFuncSetAttribute(k1_reduce, cudaFuncAttributeMaxDynamicSharedMemorySize, smem_k1);

    k1_reduce<<<BZ * SPLITS, TPB, smem_k1>>>(feat, W, idx, pred);
    k2_final<<<BZ, 256>>>(pred, cla, seg);
    k3_out<<<1, BZ>>>(out);
}